// round 15
// baseline (speedup 1.0000x reference)
#include <cuda_runtime.h>
#include <cuda_bf16.h>
#include <cstdint>
#include <math.h>

#define BB 2
#define CC 128
#define WW 96
#define HWD 9216
#define TQ 128
#define TK2 64                // columns per k tile
#define NT (HWD/TK2)          // 144 tiles
#define NTHREADS 512
#define SP 136                // padded smem row stride in bf16
#define SPB (SP*2)            // 272 bytes
#define TILEB (128*SPB)       // 34816 B: Q tile (128 rows) or one stage (64 hi + 64 lo)
#define NSTG 4

// Decomposed, normalized features: [B][HW][C] bf16, row-major.
__device__ __nv_bfloat16 g_qhi[BB*HWD*CC];
__device__ __nv_bfloat16 g_qlo[BB*HWD*CC];
__device__ __nv_bfloat16 g_khi[BB*HWD*CC];
__device__ __nv_bfloat16 g_klo[BB*HWD*CC];

// ---------------------------------------------------------------------------
// exp(s*a), a in [-1.02,1.02], s = 1/(sqrt(128)*0.1). Degree-7 Taylor, scale
// folded in; pure FMA pipe. |rel err| < 1e-5 on the domain (tolerance 1e-3).
// Valid since unit vectors => |dot|<=1, the ref's +-50 clamp never binds.
// ---------------------------------------------------------------------------
__device__ __forceinline__ float exp_scaled(float a) {
    const float c7 = 8.362471e-5f;
    const float c6 = 6.622738e-4f;
    const float c5 = 4.495664e-3f;
    const float c4 = 2.543132e-2f;
    const float c3 = 1.150890e-1f;
    const float c2 = 3.90625e-1f;       // s^2/2 (s^2 = 0.78125 exact)
    const float c1 = 0.8838834764831844f;
    float p = c7;
    p = fmaf(p, a, c6); p = fmaf(p, a, c5); p = fmaf(p, a, c4);
    p = fmaf(p, a, c3); p = fmaf(p, a, c2); p = fmaf(p, a, c1);
    p = fmaf(p, a, 1.0f);
    return p;
}

// ---------------------------------------------------------------------------
// PTX helpers (baseline PTX only)
// ---------------------------------------------------------------------------
__device__ __forceinline__ uint32_t smem_u32(const void* p) {
    uint32_t a;
    asm("{ .reg .u64 t; cvta.to.shared.u64 t, %1; cvt.u32.u64 %0, t; }" : "=r"(a) : "l"(p));
    return a;
}
__device__ __forceinline__ void mbar_init(uint32_t a, uint32_t n) {
    asm volatile("mbarrier.init.shared.b64 [%0], %1;" :: "r"(a), "r"(n) : "memory");
}
__device__ __forceinline__ void mbar_expect_tx(uint32_t a, uint32_t bytes) {
    asm volatile("mbarrier.arrive.expect_tx.shared.b64 _, [%0], %1;"
                 :: "r"(a), "r"(bytes) : "memory");
}
__device__ __forceinline__ void mbar_wait(uint32_t addr, uint32_t parity) {
    uint32_t done;
    asm volatile(
        "{\n\t.reg .pred p;\n\t"
        "mbarrier.try_wait.parity.acquire.cta.shared::cta.b64 p, [%1], %2;\n\t"
        "selp.b32 %0, 1, 0, p;\n\t}"
        : "=r"(done) : "r"(addr), "r"(parity) : "memory");
    if (!done) {
        asm volatile(
            "{\n\t.reg .pred P1;\n\t"
            "WAIT_LOOP_%=:\n\t"
            "mbarrier.try_wait.parity.acquire.cta.shared::cta.b64 P1, [%0], %1, 0x989680;\n\t"
            "@P1 bra.uni WAIT_DONE_%=;\n\t"
            "bra.uni WAIT_LOOP_%=;\n\t"
            "WAIT_DONE_%=:\n\t}"
            :: "r"(addr), "r"(parity) : "memory");
    }
}
__device__ __forceinline__ void bulk_copy(uint32_t dst, const void* src, uint32_t mbar) {
    asm volatile(
        "cp.async.bulk.shared::cta.global.mbarrier::complete_tx::bytes [%0], [%1], %2, [%3];"
        :: "r"(dst), "l"(src), "n"(256), "r"(mbar) : "memory");
}

// mma.sync m16n8k16 row.col bf16 -> fp32
#define MMA16816(d, a, b) \
    asm volatile("mma.sync.aligned.m16n8k16.row.col.f32.bf16.bf16.f32 " \
        "{%0,%1,%2,%3}, {%4,%5,%6,%7}, {%8,%9}, {%0,%1,%2,%3};" \
        : "+f"((d)[0]), "+f"((d)[1]), "+f"((d)[2]), "+f"((d)[3]) \
        : "r"((a)[0]), "r"((a)[1]), "r"((a)[2]), "r"((a)[3]), \
          "r"((b)[0]), "r"((b)[1]))

// ---------------------------------------------------------------------------
// Kernel 1: normalize + transpose + split-bf16 decompose.
// ---------------------------------------------------------------------------
__global__ void __launch_bounds__(256)
decomp_kernel(const float* __restrict__ fL, const float* __restrict__ fR) {
    __shared__ float s[CC*129];
    __shared__ float s_part[256];
    __shared__ float s_inv[128];

    const int pbase = blockIdx.x * 128;
    const int b     = blockIdx.y;
    const float* src = (blockIdx.z ? fR : fL) + (size_t)b * CC * HWD;
    __nv_bfloat16* dhi = blockIdx.z ? g_khi : g_qhi;
    __nv_bfloat16* dlo = blockIdx.z ? g_klo : g_qlo;
    const int tid = threadIdx.x;

    for (int idx = tid; idx < CC*32; idx += 256) {
        int c  = idx >> 5;
        int p4 = (idx & 31) << 2;
        float4 v = *reinterpret_cast<const float4*>(src + (size_t)c*HWD + pbase + p4);
        float* d = s + c*129 + p4;
        d[0]=v.x; d[1]=v.y; d[2]=v.z; d[3]=v.w;
    }
    __syncthreads();
    {
        int pos = tid & 127, half = tid >> 7;
        float ss = 0.f;
#pragma unroll 8
        for (int c = half*64; c < half*64 + 64; ++c) { float v = s[c*129 + pos]; ss += v*v; }
        s_part[tid] = ss;
    }
    __syncthreads();
    if (tid < 128)
        s_inv[tid] = 1.0f / fmaxf(sqrtf(s_part[tid] + s_part[tid+128]), 1e-6f);
    __syncthreads();

    for (int idx = tid; idx < 128*64; idx += 256) {
        int c2 = idx & 63, pos = idx >> 6;
        float inv = s_inv[pos];
        float f0 = s[(2*c2  )*129 + pos] * inv;
        float f1 = s[(2*c2+1)*129 + pos] * inv;
        __nv_bfloat162 h = __floats2bfloat162_rn(f0, f1);
        float l0 = f0 - __bfloat162float(h.x);
        float l1 = f1 - __bfloat162float(h.y);
        __nv_bfloat162 l = __floats2bfloat162_rn(l0, l1);
        size_t o = ((size_t)b*HWD + pbase + pos) * CC + 2*c2;
        *reinterpret_cast<uint32_t*>(&dhi[o]) = *reinterpret_cast<const uint32_t*>(&h);
        *reinterpret_cast<uint32_t*>(&dlo[o]) = *reinterpret_cast<const uint32_t*>(&l);
    }
}

// ---------------------------------------------------------------------------
// Kernel 2: software-pipelined mma.sync correlation + one-pass softmax.
// 16 warps = 4(m:32 rows) x 4(n:16 cols) over 128q x 64k tiles, 4 stages.
// Double-buffered accumulators: fold of tile t-1 is interleaved INSIDE the
// ks loop of tile t's MMAs -> tensor and FMA pipes overlap deterministically
// within each warp (no reliance on cross-group scheduling).
// smem: Qhi | Qlo | stage0..3 | mbarriers
// ---------------------------------------------------------------------------
extern __shared__ char dsm[];

__global__ void __launch_bounds__(NTHREADS, 1)
corr_kernel(float* __restrict__ out) {
    const int tid  = threadIdx.x;
    const int wid  = tid >> 5;
    const int lane = tid & 31;
    const int g    = lane >> 2;
    const int tig  = lane & 3;
    const int wm   = wid >> 2;        // 0..3: rows wm*32..+31
    const int wn   = wid & 3;         // 0..3: cols wn*16..+15
    const int b     = blockIdx.y;
    const int qbase = blockIdx.x * TQ;

    char* sQhi = dsm;
    char* sQlo = dsm + TILEB;
    char* sStg = dsm + 2*TILEB;            // NSTG stages of TILEB
    const uint32_t mbar0 = smem_u32(dsm) + (uint32_t)((2+NSTG)*TILEB);
    const uint32_t stg0  = smem_u32(sStg);

    const __nv_bfloat16* qhi  = g_qhi + ((size_t)b*HWD + qbase) * CC;
    const __nv_bfloat16* qlo  = g_qlo + ((size_t)b*HWD + qbase) * CC;
    const __nv_bfloat16* khiB = g_khi + (size_t)b*HWD*CC;
    const __nv_bfloat16* kloB = g_klo + (size_t)b*HWD*CC;

    if (tid == 0)
        for (int j = 0; j < NSTG; ++j) mbar_init(mbar0 + j*8, 1);

    // ---- load Q tiles ----
    for (int idx = tid; idx < 128*16; idx += NTHREADS) {
        int row = idx >> 4, c4 = idx & 15;
        *reinterpret_cast<float4*>(sQhi + row*SPB + c4*16) =
            reinterpret_cast<const float4*>(qhi + (size_t)row*CC)[c4];
        *reinterpret_cast<float4*>(sQlo + row*SPB + c4*16) =
            reinterpret_cast<const float4*>(qlo + (size_t)row*CC)[c4];
    }
    __syncthreads();   // mbarriers + Q visible

    // ---- stage loader (warp 0, warp-collective): tile i -> stage j ----
    auto issue_load = [&](int i, int j) {
        const uint32_t mb = mbar0 + j*8;
        if (lane == 0) mbar_expect_tx(mb, 128*256);
        __syncwarp();
        const uint32_t dst = stg0 + j*TILEB;
#pragma unroll
        for (int r = lane; r < 64; r += 32) {
            bulk_copy(dst + r*SPB,        khiB + (size_t)(i*TK2 + r)*CC, mb);
            bulk_copy(dst + (64+r)*SPB,   kloB + (size_t)(i*TK2 + r)*CC, mb);
        }
    };
    if (wid == 0)
        for (int j = 0; j < NSTG; ++j) issue_load(j, j);

    // per-lane softmax accumulators: 4 row slots (2 mb x 2 half-rows)
    float pS[4], pX[4], pY[4], pM[4];
#pragma unroll
    for (int i = 0; i < 4; ++i) { pS[i]=0.f; pX[i]=0.f; pY[i]=0.f; pM[i]=-4.f; }

    const int aoff = (wm*32 + g)*SPB + tig*4;       // A-frag base (within Q)
    const int boff = (wn*16 + g)*SPB + tig*4;       // B-frag base (within stage)

    // fold one acc element f (0..15) of tile pt into the running softmax
    auto fold_one = [&](float (&accP)[2][2][4], int pt, int f) {
        const int mb = f >> 3, nb = (f >> 2) & 1, r = f & 3;
        const int col = pt*TK2 + wn*16 + nb*8 + tig*2 + (r & 1);
        const int cyi = col / WW;
        const float cy = (float)cyi;
        const float cx = (float)(col - cyi*WW);
        const int slot = mb*2 + (r >> 1);
        float d = accP[mb][nb][r];
        d = fminf(fmaxf(d, -1.02f), 1.02f);
        float e = exp_scaled(d);
        pS[slot] += e;
        pX[slot] += e * cx;
        pY[slot] += e * cy;
        pM[slot]  = fmaxf(pM[slot], d);
    };

    // one tile: MMA tile t into accC, fold accP (tile t-1) interleaved
    auto body = [&](float (&accC)[2][2][4], float (&accP)[2][2][4],
                    int t, bool doFold) {
        const int st = t & (NSTG-1);
        mbar_wait(mbar0 + st*8, (uint32_t)((t >> 2) & 1));
        const char* Shi = sStg + st*TILEB;
        const char* Slo = Shi + 64*SPB;
        const int pt = t - 1;

#pragma unroll
        for (int mb = 0; mb < 2; ++mb)
#pragma unroll
            for (int nb = 0; nb < 2; ++nb)
#pragma unroll
                for (int r = 0; r < 4; ++r) accC[mb][nb][r] = 0.f;

#pragma unroll
        for (int ks = 0; ks < 8; ++ks) {
            const int co = ks*32;   // 16 chans * 2B
            uint32_t bh0[2], bh1[2], bl0[2], bl1[2];
            {
                const char* p0 = Shi + boff + co;
                bh0[0] = *reinterpret_cast<const uint32_t*>(p0);
                bh0[1] = *reinterpret_cast<const uint32_t*>(p0 + 16);
                bh1[0] = *reinterpret_cast<const uint32_t*>(p0 + 8*SPB);
                bh1[1] = *reinterpret_cast<const uint32_t*>(p0 + 8*SPB + 16);
                const char* p1 = Slo + boff + co;
                bl0[0] = *reinterpret_cast<const uint32_t*>(p1);
                bl0[1] = *reinterpret_cast<const uint32_t*>(p1 + 16);
                bl1[0] = *reinterpret_cast<const uint32_t*>(p1 + 8*SPB);
                bl1[1] = *reinterpret_cast<const uint32_t*>(p1 + 8*SPB + 16);
            }
#pragma unroll
            for (int mb = 0; mb < 2; ++mb) {
                uint32_t a[4];
                const char* pa = sQhi + aoff + mb*16*SPB + co;
                a[0] = *reinterpret_cast<const uint32_t*>(pa);
                a[1] = *reinterpret_cast<const uint32_t*>(pa + 8*SPB);
                a[2] = *reinterpret_cast<const uint32_t*>(pa + 16);
                a[3] = *reinterpret_cast<const uint32_t*>(pa + 8*SPB + 16);
                MMA16816(accC[mb][0], a, bh0);
                MMA16816(accC[mb][1], a, bh1);
                MMA16816(accC[mb][0], a, bl0);
                MMA16816(accC[mb][1], a, bl1);
                const char* pl = sQlo + aoff + mb*16*SPB + co;
                a[0] = *reinterpret_cast<const uint32_t*>(pl);
                a[1] = *reinterpret_cast<const uint32_t*>(pl + 8*SPB);
                a[2] = *reinterpret_cast<const uint32_t*>(pl + 16);
                a[3] = *reinterpret_cast<const uint32_t*>(pl + 8*SPB + 16);
                MMA16816(accC[mb][0], a, bh0);
                MMA16816(accC[mb][1], a, bh1);
            }
            if (doFold) {               // 2 logits of the PREVIOUS tile per ks
                fold_one(accP, pt, ks*2);
                fold_one(accP, pt, ks*2 + 1);
            }
        }

        __syncthreads();                // all warps done reading stage st
        if (wid == 0 && t + NSTG < NT) issue_load(t + NSTG, st);
    };

    float accA[2][2][4], accB[2][2][4];
    body(accA, accB, 0, false);
    body(accB, accA, 1, true);
    for (int p = 1; p < NT/2; ++p) {
        body(accA, accB, 2*p,     true);
        body(accB, accA, 2*p + 1, true);
    }
    // last tile's logits (tile NT-1, in accB)
#pragma unroll
    for (int f = 0; f < 16; ++f) fold_one(accB, NT - 1, f);

    // ---- reduce across tig lanes (same row, different cols) ----
#pragma unroll
    for (int s = 0; s < 4; ++s) {
#pragma unroll
        for (int d = 1; d <= 2; d <<= 1) {
            pS[s] += __shfl_xor_sync(0xffffffff, pS[s], d);
            pX[s] += __shfl_xor_sync(0xffffffff, pX[s], d);
            pY[s] += __shfl_xor_sync(0xffffffff, pY[s], d);
            pM[s]  = fmaxf(pM[s], __shfl_xor_sync(0xffffffff, pM[s], d));
        }
    }

    // ---- cross-warp (wn) reduction via smem (reuse Q region) ----
    float* red = reinterpret_cast<float*>(dsm);   // [4 stats][128 rows][4 wn]
    if (tig == 0) {
#pragma unroll
        for (int s = 0; s < 4; ++s) {
            int row = wm*32 + (s >> 1)*16 + (s & 1)*8 + g;
            red[(0*128 + row)*4 + wn] = pS[s];
            red[(1*128 + row)*4 + wn] = pX[s];
            red[(2*128 + row)*4 + wn] = pY[s];
            red[(3*128 + row)*4 + wn] = pM[s];
        }
    }
    __syncthreads();

    if (tid < 128) {
        const int row = tid;
        float s = 0.f, xs = 0.f, ys = 0.f, m = -4.f;
#pragma unroll
        for (int t = 0; t < 4; ++t) {
            s  += red[(0*128 + row)*4 + t];
            xs += red[(1*128 + row)*4 + t];
            ys += red[(2*128 + row)*4 + t];
            m   = fmaxf(m, red[(3*128 + row)*4 + t]);
        }
        const int p = qbase + row;
        const float xsrc = (float)(p % WW);
        const float ysrc = (float)(p / WW);
        const float invs = 1.0f / s;
        out[((size_t)b*2 + 0)*HWD + p] = xs * invs - xsrc;
        out[((size_t)b*2 + 1)*HWD + p] = ys * invs - ysrc;
        out[(size_t)BB*2*HWD + (size_t)b*HWD + p] = exp_scaled(m) * invs;
    }
}

// ---------------------------------------------------------------------------
extern "C" void kernel_launch(void* const* d_in, const int* in_sizes, int n_in,
                              void* d_out, int out_size) {
    const float* fL = (const float*)d_in[0];
    const float* fR = (const float*)d_in[1];
    float* out = (float*)d_out;

    {
        dim3 grid(HWD/128, BB, 2);
        decomp_kernel<<<grid, 256>>>(fL, fR);
    }
    {
        const int smem_bytes = (2+NSTG)*TILEB + 64;   // 208960
        cudaFuncSetAttribute(corr_kernel,
                             cudaFuncAttributeMaxDynamicSharedMemorySize, smem_bytes);
        dim3 grid(HWD / TQ, BB);
        corr_kernel<<<grid, NTHREADS, smem_bytes>>>(out);
    }
}

// round 17
// speedup vs baseline: 2.5925x; 2.5925x over previous
#include <cuda_runtime.h>
#include <cuda_fp16.h>
#include <cstdint>
#include <math.h>

#define BB 2
#define CC 128
#define WW 96
#define HWD 9216
#define TQ 128
#define TK2 64                // columns per group tile
#define NT (HWD/TK2)          // 144 tiles; group A even, group B odd
#define NTHREADS 512
#define SP 136                // padded smem row stride in fp16
#define SPB (SP*2)            // 272 bytes
#define QTILEB (128*SPB)      // 34816 B: one Q tile (hi or lo), 128 rows
#define SSTGB (64*SPB)        // 17408 B: one k stage (64 rows, hi only)
#define LOG2E_S 1.27517402f   // s/ln2, s = 1/(sqrt(128)*0.1)

// Normalized features: q split fp16 hi+lo, k single fp16. [B][HW][C] row-major.
__device__ __half g_qhi[BB*HWD*CC];
__device__ __half g_qlo[BB*HWD*CC];
__device__ __half g_khi[BB*HWD*CC];

// ---------------------------------------------------------------------------
// PTX helpers (baseline PTX only: mbarrier, cp.async.bulk, mma.sync, ldmatrix)
// ---------------------------------------------------------------------------
__device__ __forceinline__ uint32_t smem_u32(const void* p) {
    uint32_t a;
    asm("{ .reg .u64 t; cvta.to.shared.u64 t, %1; cvt.u32.u64 %0, t; }" : "=r"(a) : "l"(p));
    return a;
}
__device__ __forceinline__ void mbar_init(uint32_t a, uint32_t n) {
    asm volatile("mbarrier.init.shared.b64 [%0], %1;" :: "r"(a), "r"(n) : "memory");
}
__device__ __forceinline__ void mbar_expect_tx(uint32_t a, uint32_t bytes) {
    asm volatile("mbarrier.arrive.expect_tx.shared.b64 _, [%0], %1;"
                 :: "r"(a), "r"(bytes) : "memory");
}
__device__ __forceinline__ void mbar_wait(uint32_t addr, uint32_t parity) {
    uint32_t done;
    asm volatile(
        "{\n\t.reg .pred p;\n\t"
        "mbarrier.try_wait.parity.acquire.cta.shared::cta.b64 p, [%1], %2;\n\t"
        "selp.b32 %0, 1, 0, p;\n\t}"
        : "=r"(done) : "r"(addr), "r"(parity) : "memory");
    if (!done) {
        asm volatile(
            "{\n\t.reg .pred P1;\n\t"
            "WAIT_LOOP_%=:\n\t"
            "mbarrier.try_wait.parity.acquire.cta.shared::cta.b64 P1, [%0], %1, 0x989680;\n\t"
            "@P1 bra.uni WAIT_DONE_%=;\n\t"
            "bra.uni WAIT_LOOP_%=;\n\t"
            "WAIT_DONE_%=:\n\t}"
            :: "r"(addr), "r"(parity) : "memory");
    }
}
__device__ __forceinline__ void bulk_copy(uint32_t dst, const void* src, uint32_t mbar) {
    asm volatile(
        "cp.async.bulk.shared::cta.global.mbarrier::complete_tx::bytes [%0], [%1], %2, [%3];"
        :: "r"(dst), "l"(src), "n"(256), "r"(mbar) : "memory");
}
__device__ __forceinline__ void group_bar(uint32_t id) {
    asm volatile("bar.sync %0, %1;" :: "r"(id), "n"(256) : "memory");
}
__device__ __forceinline__ float ex2f(float x) {
    float r;
    asm("ex2.approx.f32 %0, %1;" : "=f"(r) : "f"(x));
    return r;
}

#define LDMATRIX_X4(r0, r1, r2, r3, addr) \
    asm volatile("ldmatrix.sync.aligned.m8n8.x4.shared.b16 {%0,%1,%2,%3}, [%4];" \
        : "=r"(r0), "=r"(r1), "=r"(r2), "=r"(r3) : "r"(addr))

// mma.sync m16n8k16 row.col fp16 -> fp32
#define MMA16816(d, a0, a1, a2, a3, b0, b1) \
    asm volatile("mma.sync.aligned.m16n8k16.row.col.f32.f16.f16.f32 " \
        "{%0,%1,%2,%3}, {%4,%5,%6,%7}, {%8,%9}, {%0,%1,%2,%3};" \
        : "+f"((d)[0]), "+f"((d)[1]), "+f"((d)[2]), "+f"((d)[3]) \
        : "r"(a0), "r"(a1), "r"(a2), "r"(a3), "r"(b0), "r"(b1))

// ---------------------------------------------------------------------------
// Kernel 1: normalize + transpose + fp16 split (q: hi+lo; k: hi only).
// grid: (HWD/128, BB, 2{L,R})
// ---------------------------------------------------------------------------
__global__ void __launch_bounds__(256)
decomp_kernel(const float* __restrict__ fL, const float* __restrict__ fR) {
    __shared__ float s[CC*129];
    __shared__ float s_part[256];
    __shared__ float s_inv[128];

    const int pbase = blockIdx.x * 128;
    const int b     = blockIdx.y;
    const int isK   = blockIdx.z;
    const float* src = (isK ? fR : fL) + (size_t)b * CC * HWD;
    const int tid = threadIdx.x;

    for (int idx = tid; idx < CC*32; idx += 256) {
        int c  = idx >> 5;
        int p4 = (idx & 31) << 2;
        float4 v = *reinterpret_cast<const float4*>(src + (size_t)c*HWD + pbase + p4);
        float* d = s + c*129 + p4;
        d[0]=v.x; d[1]=v.y; d[2]=v.z; d[3]=v.w;
    }
    __syncthreads();
    {
        int pos = tid & 127, half = tid >> 7;
        float ss = 0.f;
#pragma unroll 8
        for (int c = half*64; c < half*64 + 64; ++c) { float v = s[c*129 + pos]; ss += v*v; }
        s_part[tid] = ss;
    }
    __syncthreads();
    if (tid < 128)
        s_inv[tid] = 1.0f / fmaxf(sqrtf(s_part[tid] + s_part[tid+128]), 1e-6f);
    __syncthreads();

    for (int idx = tid; idx < 128*64; idx += 256) {
        int c2 = idx & 63, pos = idx >> 6;
        float inv = s_inv[pos];
        float f0 = s[(2*c2  )*129 + pos] * inv;
        float f1 = s[(2*c2+1)*129 + pos] * inv;
        __half2 h = __floats2half2_rn(f0, f1);
        size_t o = ((size_t)b*HWD + pbase + pos) * CC + 2*c2;
        if (isK) {
            *reinterpret_cast<uint32_t*>(&g_khi[o]) = *reinterpret_cast<const uint32_t*>(&h);
        } else {
            float l0 = f0 - __half2float(__low2half(h));
            float l1 = f1 - __half2float(__high2half(h));
            __half2 l = __floats2half2_rn(l0, l1);
            *reinterpret_cast<uint32_t*>(&g_qhi[o]) = *reinterpret_cast<const uint32_t*>(&h);
            *reinterpret_cast<uint32_t*>(&g_qlo[o]) = *reinterpret_cast<const uint32_t*>(&l);
        }
    }
}

// ---------------------------------------------------------------------------
// Kernel 2: dual-group mma.sync correlation + one-pass softmax (R14 structure).
// 16 warps: group A (0-7) even 64-col k-tiles, group B (8-15) odd tiles.
// Per group: 2(wm:64 rows) x 4(wn:16 cols). fp16 2-product: qhi*k + qlo*k.
// ldmatrix fragment loads; ex2.approx softmax fold.
// smem: Qhi | Qlo | stage0..3 (A:0,1  B:2,3) | mbarriers
// ---------------------------------------------------------------------------
extern __shared__ char dsm[];

__global__ void __launch_bounds__(NTHREADS, 1)
corr_kernel(float* __restrict__ out) {
    const int tid  = threadIdx.x;
    const int wid  = tid >> 5;
    const int lane = tid & 31;
    const int g    = lane >> 2;
    const int tig  = lane & 3;
    const int grp  = wid >> 3;        // 0 = A, 1 = B
    const int wg   = wid & 7;         // warp within group
    const int wm   = wg >> 2;         // 0..1 (64 rows each)
    const int wn   = wg & 3;          // 0..3 (16 cols each)
    const int b     = blockIdx.y;
    const int qbase = blockIdx.x * TQ;

    char* sQhi = dsm;
    char* sQlo = dsm + QTILEB;
    char* sStg = dsm + 2*QTILEB;           // 4 stages of SSTGB
    const uint32_t mbar0 = smem_u32(dsm) + (uint32_t)(2*QTILEB + 4*SSTGB);
    const uint32_t stg0  = smem_u32(sStg);

    const __half* qhi  = g_qhi + ((size_t)b*HWD + qbase) * CC;
    const __half* qlo  = g_qlo + ((size_t)b*HWD + qbase) * CC;
    const __half* khiB = g_khi + (size_t)b*HWD*CC;

    if (tid == 0)
        for (int j = 0; j < 4; ++j) mbar_init(mbar0 + j*8, 1);

    // ---- load Q tiles (rows = 256B = 16 float4) ----
    for (int idx = tid; idx < 128*16; idx += NTHREADS) {
        int row = idx >> 4, c4 = idx & 15;
        *reinterpret_cast<float4*>(sQhi + row*SPB + c4*16) =
            reinterpret_cast<const float4*>(qhi + (size_t)row*CC)[c4];
        *reinterpret_cast<float4*>(sQlo + row*SPB + c4*16) =
            reinterpret_cast<const float4*>(qlo + (size_t)row*CC)[c4];
    }
    __syncthreads();   // mbarriers + Q visible to all

    // ---- per-group stage loader (first warp of group): tile i -> stage j ----
    const bool is_loader = (wg == 0);
    auto issue_load = [&](int i, int j) {
        const uint32_t mb = mbar0 + j*8;
        if (lane == 0) mbar_expect_tx(mb, 64*256);
        __syncwarp();
        const uint32_t dst = stg0 + j*SSTGB;
#pragma unroll
        for (int r = lane; r < 64; r += 32)
            bulk_copy(dst + r*SPB, khiB + (size_t)(i*TK2 + r)*CC, mb);
    };

    if (is_loader) {
        issue_load(grp,     2*grp);
        issue_load(grp + 2, 2*grp + 1);
    }

    uint32_t ph[2] = {0, 0};

    // per-lane softmax accumulators: 8 row slots (4 mb x 2 half-rows)
    float pS[8], pX[8], pY[8], pM[8];
#pragma unroll
    for (int i = 0; i < 8; ++i) { pS[i]=0.f; pX[i]=0.f; pY[i]=0.f; pM[i]=-4.f; }

    // ldmatrix per-lane addresses
    // A (m16k16 x4): lanes 0-15 -> rows 0-15, lanes 16-31 -> same rows +16B
    const uint32_t aRow = (uint32_t)((wm*64 + (lane & 15)) * SPB + ((lane >> 4) & 1) * 16);
    const uint32_t aHiA = smem_u32(sQhi) + aRow;
    const uint32_t aLoA = smem_u32(sQlo) + aRow;
    // B (n8k16 x4, two nb blocks): lanes {0-7,8-15,16-23,24-31} ->
    // (n0-7,+0B) (n0-7,+16B) (n8-15,+0B) (n8-15,+16B)
    const uint32_t bRow = (uint32_t)((wn*16 + (lane & 7) + ((lane >> 4) & 1) * 8) * SPB
                                     + ((lane >> 3) & 1) * 16);

    for (int t = 0; t < NT/2; ++t) {
        const int i  = grp + 2*t;         // this group's tile index
        const int bs = t & 1;
        const int j  = 2*grp + bs;        // stage slot
        mbar_wait(mbar0 + j*8, ph[bs]); ph[bs] ^= 1;

        const uint32_t bBase = stg0 + j*SSTGB + bRow;

        float acc[4][2][4];
#pragma unroll
        for (int mb = 0; mb < 4; ++mb)
#pragma unroll
            for (int nb = 0; nb < 2; ++nb)
#pragma unroll
                for (int r = 0; r < 4; ++r) acc[mb][nb][r] = 0.f;

#pragma unroll
        for (int ks = 0; ks < 8; ++ks) {
            const uint32_t co = ks*32;    // 16 chans * 2B
            uint32_t b0, b1, b2, b3;
            LDMATRIX_X4(b0, b1, b2, b3, bBase + co);
#pragma unroll
            for (int mb = 0; mb < 4; ++mb) {
                const uint32_t moff = mb*16*SPB + co;
                uint32_t a0, a1, a2, a3;
                LDMATRIX_X4(a0, a1, a2, a3, aHiA + moff);
                MMA16816(acc[mb][0], a0, a1, a2, a3, b0, b1);
                MMA16816(acc[mb][1], a0, a1, a2, a3, b2, b3);
                LDMATRIX_X4(a0, a1, a2, a3, aLoA + moff);
                MMA16816(acc[mb][0], a0, a1, a2, a3, b0, b1);
                MMA16816(acc[mb][1], a0, a1, a2, a3, b2, b3);
            }
        }

        group_bar(1 + grp);               // all group warps done reading stage j
        if (is_loader && i + 4 < NT) issue_load(i + 4, j);

        // ---- fold 64x16 warp-tile logits (ex2.approx, overlaps other group) ----
#pragma unroll
        for (int nb = 0; nb < 2; ++nb) {
            const int col = i*TK2 + wn*16 + nb*8 + tig*2;   // even, +1 never wraps
            const int cyi = col / WW;
            const float cy  = (float)cyi;
            const float cx0 = (float)(col - cyi*WW);
#pragma unroll
            for (int mb = 0; mb < 4; ++mb) {
#pragma unroll
                for (int r = 0; r < 4; ++r) {
                    const int slot = mb*2 + (r >> 1);
                    const float cx = (r & 1) ? (cx0 + 1.f) : cx0;
                    const float d = acc[mb][nb][r];       // in [-1.001, 1.001]
                    const float e = ex2f(d * LOG2E_S);    // exp(s*d)
                    pS[slot] += e;
                    pX[slot] = fmaf(e, cx, pX[slot]);
                    pY[slot] = fmaf(e, cy, pY[slot]);
                    pM[slot]  = fmaxf(pM[slot], d);
                }
            }
        }
    }

    // ---- reduce across tig lanes (same row, different cols) ----
#pragma unroll
    for (int s = 0; s < 8; ++s) {
#pragma unroll
        for (int d = 1; d <= 2; d <<= 1) {
            pS[s] += __shfl_xor_sync(0xffffffff, pS[s], d);
            pX[s] += __shfl_xor_sync(0xffffffff, pX[s], d);
            pY[s] += __shfl_xor_sync(0xffffffff, pY[s], d);
            pM[s]  = fmaxf(pM[s], __shfl_xor_sync(0xffffffff, pM[s], d));
        }
    }

    // ---- cross-warp & cross-group reduction via smem (reuse Q region) ----
    __syncthreads();                       // both groups fully done with Q/stages
    float* red = reinterpret_cast<float*>(dsm);   // [4 stats][128 rows][8]
    if (tig == 0) {
        const int pidx = grp*4 + wn;
#pragma unroll
        for (int s = 0; s < 8; ++s) {
            int row = wm*64 + (s >> 1)*16 + (s & 1)*8 + g;
            red[(0*128 + row)*8 + pidx] = pS[s];
            red[(1*128 + row)*8 + pidx] = pX[s];
            red[(2*128 + row)*8 + pidx] = pY[s];
            red[(3*128 + row)*8 + pidx] = pM[s];
        }
    }
    __syncthreads();

    if (tid < 128) {
        const int row = tid;
        float s = 0.f, xs = 0.f, ys = 0.f, m = -4.f;
#pragma unroll
        for (int t = 0; t < 8; ++t) {
            s  += red[(0*128 + row)*8 + t];
            xs += red[(1*128 + row)*8 + t];
            ys += red[(2*128 + row)*8 + t];
            m   = fmaxf(m, red[(3*128 + row)*8 + t]);
        }
        const int p = qbase + row;
        const float xsrc = (float)(p % WW);
        const float ysrc = (float)(p / WW);
        const float invs = 1.0f / s;
        out[((size_t)b*2 + 0)*HWD + p] = xs * invs - xsrc;
        out[((size_t)b*2 + 1)*HWD + p] = ys * invs - ysrc;
        out[(size_t)BB*2*HWD + (size_t)b*HWD + p] = ex2f(m * LOG2E_S) * invs;
    }
}

// ---------------------------------------------------------------------------
extern "C" void kernel_launch(void* const* d_in, const int* in_sizes, int n_in,
                              void* d_out, int out_size) {
    const float* fL = (const float*)d_in[0];
    const float* fR = (const float*)d_in[1];
    float* out = (float*)d_out;

    {
        dim3 grid(HWD/128, BB, 2);
        decomp_kernel<<<grid, 256>>>(fL, fR);
    }
    {
        const int smem_bytes = 2*QTILEB + 4*SSTGB + 64;   // 139328
        cudaFuncSetAttribute(corr_kernel,
                             cudaFuncAttributeMaxDynamicSharedMemorySize, smem_bytes);
        dim3 grid(HWD / TQ, BB);
        corr_kernel<<<grid, NTHREADS, smem_bytes>>>(out);
    }
}